// round 1
// baseline (speedup 1.0000x reference)
#include <cuda_runtime.h>
#include <math.h>

#define NMAX 50000
#define EMAX 800000
#define ETOT (NMAX + EMAX)
#define FULLM 0xffffffffu

// ---------------- scratch (static device globals: no allocation allowed) ----
__device__ int   d_is64;
__device__ int   d_deg[NMAX];
__device__ int   d_rowptr[NMAX + 1];
__device__ int   d_cursor[NMAX];
__device__ int   d_col[ETOT];
__device__ float d_hA[NMAX * 128];   // feature buffer (h of current layer)
__device__ float d_hB[NMAX * 128];   // activation buffer (z of current layer)
__device__ float d_as[NMAX * 4];
__device__ float d_ad[NMAX * 4];
__device__ float d_h3[NMAX];
__device__ float d_as3[NMAX];
__device__ float d_ad3[NMAX];

// ---------------- helpers ---------------------------------------------------
__device__ __forceinline__ float lrelu(float e) { return e > 0.f ? e : 0.2f * e; }

__device__ __forceinline__ float wredsum(float v) {
#pragma unroll
    for (int o = 16; o; o >>= 1) v += __shfl_xor_sync(FULLM, v, o);
    return v;
}
__device__ __forceinline__ float wredmax(float v) {
#pragma unroll
    for (int o = 16; o; o >>= 1) v = fmaxf(v, __shfl_xor_sync(FULLM, v, o));
    return v;
}
__device__ __forceinline__ float comp4(float4 v, int h) {
    float r = v.x;
    r = (h == 1) ? v.y : r;
    r = (h == 2) ? v.z : r;
    r = (h == 3) ? v.w : r;
    return r;
}

// ---------------- dtype detect (int32 vs int64 edge_index) ------------------
__global__ void detect_k(const void* ei) {
    if (threadIdx.x == 0 && blockIdx.x == 0) {
        const int* p = (const int*)ei;
        int is64 = 1;
        for (int i = 0; i < 256; i++) {
            if (p[2 * i + 1] != 0) { is64 = 0; break; }
        }
        d_is64 = is64;
    }
}

// ---------------- CSR build -------------------------------------------------
__global__ void zero_k(int N) {
    int i = blockIdx.x * blockDim.x + threadIdx.x;
    if (i < N) d_deg[i] = 0;
}

__global__ void hist_k(const void* ei, int E, int N) {
    int e = blockIdx.x * blockDim.x + threadIdx.x;
    int tot = E + N;
    if (e >= tot) return;
    int dst;
    if (e < E) {
        if (d_is64) dst = (int)((const long long*)ei)[(long long)E + e];
        else        dst = ((const int*)ei)[E + e];
    } else {
        dst = e - E;  // self loop
    }
    atomicAdd(&d_deg[dst], 1);
}

__global__ void scan_k(int N) {
    __shared__ float dummy_pad[1];  // (unused; keeps alignment obvious)
    __shared__ int sm[1024];
    __shared__ int carry;
    if (threadIdx.x == 0) { carry = 0; d_rowptr[0] = 0; (void)dummy_pad; }
    __syncthreads();
    for (int base = 0; base < N; base += 1024) {
        int i = base + threadIdx.x;
        int v = (i < N) ? d_deg[i] : 0;
        sm[threadIdx.x] = v;
        __syncthreads();
#pragma unroll
        for (int off = 1; off < 1024; off <<= 1) {
            int t = (threadIdx.x >= off) ? sm[threadIdx.x - off] : 0;
            __syncthreads();
            sm[threadIdx.x] += t;
            __syncthreads();
        }
        int incl = sm[threadIdx.x] + carry;
        if (i < N) {
            d_rowptr[i + 1] = incl;
            d_cursor[i] = incl - v;
        }
        __syncthreads();
        if (threadIdx.x == 1023) carry = incl;
        __syncthreads();
    }
}

__global__ void scatter_k(const void* ei, int E, int N) {
    int e = blockIdx.x * blockDim.x + threadIdx.x;
    int tot = E + N;
    if (e >= tot) return;
    int src, dst;
    if (e < E) {
        if (d_is64) {
            const long long* p = (const long long*)ei;
            src = (int)p[e];
            dst = (int)p[(long long)E + e];
        } else {
            const int* p = (const int*)ei;
            src = p[e];
            dst = p[E + e];
        }
    } else {
        src = dst = e - E;
    }
    int pos = atomicAdd(&d_cursor[dst], 1);
    d_col[pos] = src;
}

// ---------------- layer 1 feature: h1 = x @ W1 (Fin=1), alphas --------------
__global__ void l1_feat_k(const float* __restrict__ x, const float* __restrict__ W1,
                          const float* __restrict__ as1, const float* __restrict__ ad1,
                          float* __restrict__ h_out, int N) {
    int n = blockIdx.x;
    if (n >= N) return;
    int j = threadIdx.x;  // 0..127, warp = head
    float xv = x[n];
    float h = xv * W1[j];
    h_out[n * 128 + j] = h;
    float ps = wredsum(h * as1[j]);
    float pd = wredsum(h * ad1[j]);
    if ((j & 31) == 0) {
        d_as[n * 4 + (j >> 5)] = ps;
        d_ad[n * 4 + (j >> 5)] = pd;
    }
}

// ---------------- layer 2 feature: h2 = z1 @ W2 (128x128), alphas -----------
// persistent blocks, W2 resident in smem, 4-node register blocking
__global__ void gemm_k(const float* __restrict__ zin, const float* __restrict__ W2,
                       const float* __restrict__ as2, const float* __restrict__ ad2,
                       float* __restrict__ h_out, int N) {
    extern __shared__ float smem[];        // [128*128 W][128*4 zt]
    float* Wsm = smem;
    float* zt  = smem + 128 * 128;
    int tid = threadIdx.x;                 // 128 threads

    // load W2 once per block
    for (int t = tid; t < 128 * 128 / 4; t += 128)
        ((float4*)Wsm)[t] = ((const float4*)W2)[t];
    __syncthreads();

    float asj = as2[tid];
    float adj = ad2[tid];
    int lane = tid & 31, head = tid >> 5;

    for (int g = blockIdx.x * 4; g < N; g += gridDim.x * 4) {
        // zt[k*4+m] = z[(g+m)*128 + k]
        for (int t = tid; t < 512; t += 128) {
            int k = t >> 2, m = t & 3;
            int node = g + m;
            zt[t] = (node < N) ? zin[node * 128 + k] : 0.f;
        }
        __syncthreads();

        float a0 = 0.f, a1 = 0.f, a2 = 0.f, a3 = 0.f;
#pragma unroll 8
        for (int k = 0; k < 128; k++) {
            float w = Wsm[k * 128 + tid];
            float4 zv = ((const float4*)zt)[k];
            a0 = fmaf(zv.x, w, a0);
            a1 = fmaf(zv.y, w, a1);
            a2 = fmaf(zv.z, w, a2);
            a3 = fmaf(zv.w, w, a3);
        }
        float acc[4] = {a0, a1, a2, a3};
#pragma unroll
        for (int m = 0; m < 4; m++) {
            int node = g + m;
            float ps = wredsum(acc[m] * asj);
            float pd = wredsum(acc[m] * adj);
            if (node < N) {
                h_out[node * 128 + tid] = acc[m];
                if (lane == 0) {
                    d_as[node * 4 + head] = ps;
                    d_ad[node * 4 + head] = pd;
                }
            }
        }
        __syncthreads();
    }
}

// ---------------- GAT aggregation (layers 1 & 2), warp per dst node ---------
// pass1: per-head max over incoming edges (lanes over edges)
// pass2: per-head softmax denominator         (lanes over edges)
// pass3: weighted message sum                 (lanes over channels, float4)
// optional fused epilogue: h3 = elu(o+b) @ W3, alpha3 (layer 2 only)
__global__ void agg_k(const float* __restrict__ h_in,
                      const float* __restrict__ bias,
                      float* __restrict__ z_out,
                      const float* __restrict__ w3,
                      const float* __restrict__ a3s, const float* __restrict__ a3d,
                      int apply_elu, int store_z, int N) {
    int w = (blockIdx.x * blockDim.x + threadIdx.x) >> 5;
    if (w >= N) return;
    int lane = threadIdx.x & 31;
    int start = d_rowptr[w], end = d_rowptr[w + 1];

    float4 adv = ((const float4*)d_ad)[w];

    // pass 1: max per head
    float m0 = -1e30f, m1 = -1e30f, m2 = -1e30f, m3 = -1e30f;
    for (int i = start + lane; i < end; i += 32) {
        int s = d_col[i];
        float4 av = ((const float4*)d_as)[s];
        m0 = fmaxf(m0, lrelu(av.x + adv.x));
        m1 = fmaxf(m1, lrelu(av.y + adv.y));
        m2 = fmaxf(m2, lrelu(av.z + adv.z));
        m3 = fmaxf(m3, lrelu(av.w + adv.w));
    }
    m0 = wredmax(m0); m1 = wredmax(m1); m2 = wredmax(m2); m3 = wredmax(m3);

    // pass 2: sum of exp per head
    float s0 = 0.f, s1 = 0.f, s2 = 0.f, s3 = 0.f;
    for (int i = start + lane; i < end; i += 32) {
        int s = d_col[i];
        float4 av = ((const float4*)d_as)[s];
        s0 += __expf(lrelu(av.x + adv.x) - m0);
        s1 += __expf(lrelu(av.y + adv.y) - m1);
        s2 += __expf(lrelu(av.z + adv.z) - m2);
        s3 += __expf(lrelu(av.w + adv.w) - m3);
    }
    s0 = wredsum(s0); s1 = wredsum(s1); s2 = wredsum(s2); s3 = wredsum(s3);

    int myh = lane >> 3;  // lane holds channels 4*lane..4*lane+3, all in head lane/8
    float mh   = comp4(make_float4(m0, m1, m2, m3), myh);
    float invh = comp4(make_float4(1.f / s0, 1.f / s1, 1.f / s2, 1.f / s3), myh);
    float adh  = comp4(adv, myh);

    // pass 3: weighted sum of source features
    float4 acc = make_float4(0.f, 0.f, 0.f, 0.f);
#pragma unroll 2
    for (int i = start; i < end; i++) {
        int s = d_col[i];
        float4 av = ((const float4*)d_as)[s];
        float wgt = __expf(lrelu(comp4(av, myh) + adh) - mh) * invh;
        float4 hv = ((const float4*)h_in)[s * 32 + lane];
        acc.x = fmaf(wgt, hv.x, acc.x);
        acc.y = fmaf(wgt, hv.y, acc.y);
        acc.z = fmaf(wgt, hv.z, acc.z);
        acc.w = fmaf(wgt, hv.w, acc.w);
    }

    float4 bv = ((const float4*)bias)[lane];
    float4 v = make_float4(acc.x + bv.x, acc.y + bv.y, acc.z + bv.z, acc.w + bv.w);
    if (apply_elu) {
        v.x = v.x > 0.f ? v.x : expm1f(v.x);
        v.y = v.y > 0.f ? v.y : expm1f(v.y);
        v.z = v.z > 0.f ? v.z : expm1f(v.z);
        v.w = v.w > 0.f ? v.w : expm1f(v.w);
    }
    if (store_z) ((float4*)z_out)[w * 32 + lane] = v;

    if (w3) {  // fused layer-3 feature: h3 = v . W3, alphas
        float4 w4 = ((const float4*)w3)[lane];
        float p = v.x * w4.x + v.y * w4.y + v.z * w4.z + v.w * w4.w;
        p = wredsum(p);
        if (lane == 0) {
            d_h3[w]  = p;
            d_as3[w] = p * a3s[0];
            d_ad3[w] = p * a3d[0];
        }
    }
}

// ---------------- layer 3 aggregation (H=1, C=1), warp per dst node ---------
__global__ void agg3_k(const float* __restrict__ b3, float* __restrict__ out, int N) {
    int w = (blockIdx.x * blockDim.x + threadIdx.x) >> 5;
    if (w >= N) return;
    int lane = threadIdx.x & 31;
    int start = d_rowptr[w], end = d_rowptr[w + 1];
    float adn = d_ad3[w];

    float m = -1e30f;
    for (int i = start + lane; i < end; i += 32) {
        int s = d_col[i];
        m = fmaxf(m, lrelu(d_as3[s] + adn));
    }
    m = wredmax(m);

    float ss = 0.f, ws = 0.f;
    for (int i = start + lane; i < end; i += 32) {
        int s = d_col[i];
        float wv = __expf(lrelu(d_as3[s] + adn) - m);
        ss += wv;
        ws += wv * d_h3[s];
    }
    ss = wredsum(ss);
    ws = wredsum(ws);
    if (lane == 0) out[w] = ws / ss + b3[0];
}

// ---------------- host launcher ---------------------------------------------
extern "C" void kernel_launch(void* const* d_in, const int* in_sizes, int n_in,
                              void* d_out, int out_size) {
    const float* x   = (const float*)d_in[0];
    const void*  ei  = d_in[1];
    const float* W1  = (const float*)d_in[2];
    const float* as1 = (const float*)d_in[3];
    const float* ad1 = (const float*)d_in[4];
    const float* b1  = (const float*)d_in[5];
    const float* W2  = (const float*)d_in[6];
    const float* as2 = (const float*)d_in[7];
    const float* ad2 = (const float*)d_in[8];
    const float* b2  = (const float*)d_in[9];
    const float* W3  = (const float*)d_in[10];
    const float* a3s = (const float*)d_in[11];
    const float* a3d = (const float*)d_in[12];
    const float* b3  = (const float*)d_in[13];
    float* out = (float*)d_out;

    int N = in_sizes[0];       // IN_C = 1
    int E = in_sizes[1] / 2;   // element count, dtype-independent
    if (N > NMAX) N = NMAX;
    if (E > EMAX) E = EMAX;
    int tot = E + N;

    float* hA; cudaGetSymbolAddress((void**)&hA, d_hA);
    float* hB; cudaGetSymbolAddress((void**)&hB, d_hB);

    detect_k<<<1, 32>>>(ei);
    zero_k<<<(N + 255) / 256, 256>>>(N);
    hist_k<<<(tot + 255) / 256, 256>>>(ei, E, N);
    scan_k<<<1, 1024>>>(N);
    scatter_k<<<(tot + 255) / 256, 256>>>(ei, E, N);

    // layer 1
    l1_feat_k<<<N, 128>>>(x, W1, as1, ad1, hA, N);
    int agg_blocks = (N * 32 + 255) / 256;
    agg_k<<<agg_blocks, 256>>>(hA, b1, hB, nullptr, nullptr, nullptr,
                               /*elu=*/1, /*store_z=*/1, N);

    // layer 2 (fused layer-3 feature in agg epilogue)
    size_t smem = (128 * 128 + 512) * sizeof(float);
    cudaFuncSetAttribute(gemm_k, cudaFuncAttributeMaxDynamicSharedMemorySize, (int)smem);
    gemm_k<<<444, 128, smem>>>(hB, W2, as2, ad2, hA, N);
    agg_k<<<agg_blocks, 256>>>(hA, b2, nullptr, W3, a3s, a3d,
                               /*elu=*/1, /*store_z=*/0, N);

    // layer 3
    agg3_k<<<agg_blocks, 256>>>(b3, out, N);
}